// round 8
// baseline (speedup 1.0000x reference)
#include <cuda_runtime.h>
#include <cuda_fp16.h>
#include <cstdint>
#include <cstddef>

// ---------------------------------------------------------------------------
// Problem constants
// ---------------------------------------------------------------------------
#define HIDN   512
#define BATCH  64
#define SEQT   256
#define MTOT   (BATCH * SEQT)       // 16384
#define G4     (4 * HIDN)           // 2048
#define NCLS   50257
#define SEQH   (BATCH * HIDN)       // 32768

// ---------------------------------------------------------------------------
// Static device scratch
// ---------------------------------------------------------------------------
__device__ float  d_xg[(size_t)MTOT * G4];               // layer-0 gate preacts
__device__ __half d_h0seq[(size_t)(SEQT + 1) * SEQH];    // slot 0 = zeros
__device__ __half d_h1seq[(size_t)(SEQT + 1) * SEQH];
__device__ float  d_hlast[SEQH];                         // h1[256] fp32
__device__ unsigned d_barrier;

__global__ void zero_h(__half* a, __half* b, int n)
{
    for (int i = blockIdx.x * blockDim.x + threadIdx.x; i < n;
         i += gridDim.x * blockDim.x) {
        a[i] = __float2half(0.0f);
        b[i] = __float2half(0.0f);
    }
}

__global__ void zero_bar()
{
    if (threadIdx.x == 0) d_barrier = 0;
}

// ---------------------------------------------------------------------------
// Common helpers
// ---------------------------------------------------------------------------
__device__ __forceinline__ unsigned f2tf(float f)
{
    unsigned u;
    asm("cvt.rna.tf32.f32 %0, %1;" : "=r"(u) : "f"(f));
    return u;
}

__device__ __forceinline__ void mma_tf32(float* c, unsigned a0, unsigned a1,
                                         unsigned a2, unsigned a3,
                                         unsigned b0, unsigned b1)
{
    asm volatile(
        "mma.sync.aligned.m16n8k8.row.col.f32.tf32.tf32.f32 "
        "{%0,%1,%2,%3}, {%4,%5,%6,%7}, {%8,%9}, {%0,%1,%2,%3};\n"
        : "+f"(c[0]), "+f"(c[1]), "+f"(c[2]), "+f"(c[3])
        : "r"(a0), "r"(a1), "r"(a2), "r"(a3), "r"(b0), "r"(b1));
}

#define LDSM4(r0, r1, r2, r3, addr)                                        \
    asm volatile("ldmatrix.sync.aligned.m8n8.x4.shared.b16 "               \
                 "{%0,%1,%2,%3}, [%4];"                                    \
                 : "=r"(r0), "=r"(r1), "=r"(r2), "=r"(r3) : "r"(addr))

#define MMA16816(c, a0, a1, a2, a3, b0, b1)                                \
    asm volatile("mma.sync.aligned.m16n8k16.row.col.f32.f16.f16.f32 "      \
                 "{%0,%1,%2,%3}, {%4,%5,%6,%7}, {%8,%9}, {%0,%1,%2,%3};"   \
                 : "+f"((c)[0]), "+f"((c)[1]), "+f"((c)[2]), "+f"((c)[3])  \
                 : "r"(a0), "r"(a1), "r"(a2), "r"(a3), "r"(b0), "r"(b1))

__device__ __forceinline__ float sigm_f(float x)
{
    return __fdividef(1.0f, 1.0f + __expf(-x));
}

__device__ __forceinline__ float tanh_f(float x)
{
    float e = __expf(2.0f * fabsf(x));
    float r = 1.0f - __fdividef(2.0f, e + 1.0f);
    return copysignf(r, x);
}

// ---------------------------------------------------------------------------
// tf32 mma GEMM, 128x128 tile, 512 threads (16 warps, 4x4), warp tile 32x32.
//   C[m][n] = sum_k A'[m][k]*B[n][k] + bias1[n] (+ bias2[n])
//   Optional embedding row gather on A. Full M/N guards. K multiple of 16.
// ---------------------------------------------------------------------------
__global__ __launch_bounds__(512)
void gemm_mma2(const float* __restrict__ A, const float* __restrict__ B,
               float* __restrict__ C,
               const float* __restrict__ bias1, const float* __restrict__ bias2,
               const int* __restrict__ gX,
               int M, int N, int K)
{
    __shared__ unsigned As[128 * 20];
    __shared__ unsigned Bs[128 * 20];

    const int tid  = threadIdx.x;
    const int lane = tid & 31;
    const int warp = tid >> 5;
    const int wm   = warp >> 2;
    const int wn   = warp & 3;
    const int gid  = lane >> 2;
    const int tig  = lane & 3;
    const int m0   = blockIdx.y * 128;
    const int n0   = blockIdx.x * 128;

    const int lrow = tid >> 2;
    const int lkq  = (tid & 3) * 4;

    const float* Ap;
    {
        int am = m0 + lrow;
        long long r;
        if (gX)          r = gX[(am & 63) * SEQT + (am >> 6)];
        else if (am < M) r = am;
        else             r = 0;
        Ap = A + (size_t)r * K + lkq;
    }
    const float* Bp;
    {
        int bn = n0 + lrow;
        Bp = B + (size_t)(bn < N ? bn : 0) * K + lkq;
    }

    float acc[2][4][4];
#pragma unroll
    for (int a = 0; a < 2; a++)
#pragma unroll
        for (int b = 0; b < 4; b++)
#pragma unroll
            for (int c = 0; c < 4; c++) acc[a][b][c] = 0.0f;

    for (int k0 = 0; k0 < K; k0 += 16) {
        float4 av = *reinterpret_cast<const float4*>(Ap + k0);
        float4 bv = *reinterpret_cast<const float4*>(Bp + k0);

        __syncthreads();
        {
            uint4 ta = make_uint4(f2tf(av.x), f2tf(av.y), f2tf(av.z), f2tf(av.w));
            uint4 tb = make_uint4(f2tf(bv.x), f2tf(bv.y), f2tf(bv.z), f2tf(bv.w));
            *reinterpret_cast<uint4*>(&As[lrow * 20 + lkq]) = ta;
            *reinterpret_cast<uint4*>(&Bs[lrow * 20 + lkq]) = tb;
        }
        __syncthreads();

#pragma unroll
        for (int kk = 0; kk < 16; kk += 8) {
            unsigned afr[2][4];
#pragma unroll
            for (int mi = 0; mi < 2; mi++) {
                int base = (wm * 32 + mi * 16 + gid) * 20 + kk + tig;
                afr[mi][0] = As[base];
                afr[mi][1] = As[base + 8 * 20];
                afr[mi][2] = As[base + 4];
                afr[mi][3] = As[base + 8 * 20 + 4];
            }
#pragma unroll
            for (int ni = 0; ni < 4; ni++) {
                int nb = (wn * 32 + ni * 8 + gid) * 20 + kk + tig;
                unsigned b0 = Bs[nb];
                unsigned b1 = Bs[nb + 4];
                mma_tf32(acc[0][ni], afr[0][0], afr[0][1], afr[0][2], afr[0][3], b0, b1);
                mma_tf32(acc[1][ni], afr[1][0], afr[1][1], afr[1][2], afr[1][3], b0, b1);
            }
        }
    }

#pragma unroll
    for (int ni = 0; ni < 4; ni++) {
        int col = n0 + wn * 32 + ni * 8 + 2 * tig;
        float bs0 = 0.f, bs1 = 0.f;
        if (col < N)     bs0 = bias1[col]     + (bias2 ? bias2[col]     : 0.0f);
        if (col + 1 < N) bs1 = bias1[col + 1] + (bias2 ? bias2[col + 1] : 0.0f);
#pragma unroll
        for (int mi = 0; mi < 2; mi++) {
            int row = m0 + wm * 32 + mi * 16 + gid;
#pragma unroll
            for (int rr = 0; rr < 2; rr++) {
                int r = row + rr * 8;
                if (r < M) {
                    if (col < N)
                        C[(size_t)r * N + col]     = acc[mi][ni][rr * 2]     + bs0;
                    if (col + 1 < N)
                        C[(size_t)r * N + col + 1] = acc[mi][ni][rr * 2 + 1] + bs1;
                }
            }
        }
    }
}

// ---------------------------------------------------------------------------
// Merged-cohort persistent LSTM: 128 blocks, each owns 4 hidden units
// (16 gate cols) of BOTH layers. Tick s (s = 1..257):
//   L0 (if s<=256): h0[s]   = F0(h0[s-1], xg0[s-1])          k=512
//   L1 (if s>=2):   h1[s-1] = F1(h1[s-2], h0[s-1])           k=1024
// One grid barrier per tick. fp16 mma m16n8k16, fp32 acc.
// Warps: wm = warp&3 (batch m16 tile), ks = warp>>2 (k-split 4).
// ---------------------------------------------------------------------------
#define SHH 520                    // h row stride (halfs)
#define SW1 1032                   // w1 row stride (halfs)
#define H1_OFF (64 * SHH)          // 33280 halfs
#define W0_OFF (H1_OFF + 64 * SHH) // 66560
#define W1_OFF (W0_OFF + 16 * SHH) // 74880
#define HALFS_TOTAL (W1_OFF + 16 * SW1)                  // 91392 halfs
#define MERGED_SMEM (HALFS_TOTAL * 2 + (8 * 68 + 8 * 16 * 65) * 4) // 218240 B

__device__ __forceinline__ void bar_red(unsigned* bar)
{
    asm volatile("red.release.gpu.global.add.u32 [%0], %1;"
                 :: "l"(bar), "r"(1u) : "memory");
}

__device__ __forceinline__ void bar_wait(unsigned* bar, unsigned target)
{
    unsigned v;
    do {
        asm volatile("ld.acquire.gpu.global.u32 %0, [%1];"
                     : "=r"(v) : "l"(bar) : "memory");
    } while (v < target);
}

__global__ __launch_bounds__(512)
void lstm_merged(const float* __restrict__ xg,     // [256][64][2048]
                 const float* __restrict__ w_hh0,
                 const float* __restrict__ w_ih1,
                 const float* __restrict__ w_hh1,
                 const float* __restrict__ b_ih1,
                 const float* __restrict__ b_hh1)
{
    extern __shared__ char smbase[];
    __half* h0_s = (__half*)smbase;            // 64 x SHH
    __half* h1_s = h0_s + H1_OFF;              // 64 x SHH
    __half* w0_s = h0_s + W0_OFF;              // 16 x SHH
    __half* w1_s = h0_s + W1_OFF;              // 16 x SW1
    float*  c_s  = (float*)(smbase + HALFS_TOTAL * 2);  // 8 x 68
    float*  g_s  = c_s + 8 * 68;               // 8 x 16 x 65

    const int tid  = threadIdx.x;
    const int blk  = blockIdx.x;               // 0..127 -> units blk*4..+3
    const int lane = tid & 31;
    const int warp = tid >> 5;
    const int wm   = warp & 3;                 // batch m16 tile
    const int ks   = warp >> 2;                // 0..3 k-split

    // ---- preload W0 (16 x 512) as fp16 ------------------------------------
    // local row r = q*4 + u  ->  w_hh0 row q*512 + blk*4 + u
#pragma unroll
    for (int i = 0; i < 4; i++) {
        int idx = tid + i * 512;               // 0..2047 float4 slots
        int r   = idx >> 7;                    // 0..15
        int kq  = (idx & 127) * 4;
        int grow = (r >> 2) * 512 + blk * 4 + (r & 3);
        float4 v = *reinterpret_cast<const float4*>(w_hh0 + (size_t)grow * 512 + kq);
        __half2* dst = reinterpret_cast<__half2*>(w0_s + r * SHH + kq);
        dst[0] = __floats2half2_rn(v.x, v.y);
        dst[1] = __floats2half2_rn(v.z, v.w);
    }
    // ---- preload W1 (16 x 1024 = [w_ih1 | w_hh1]) --------------------------
#pragma unroll
    for (int i = 0; i < 8; i++) {
        int idx = tid + i * 512;               // 0..4095 float4 slots
        int r   = idx >> 8;                    // 0..15
        int kq  = (idx & 255) * 4;
        int grow = (r >> 2) * 512 + blk * 4 + (r & 3);
        const float* src = (kq < 512)
            ? w_ih1 + (size_t)grow * 512 + kq
            : w_hh1 + (size_t)grow * 512 + (kq - 512);
        float4 v = *reinterpret_cast<const float4*>(src);
        __half2* dst = reinterpret_cast<__half2*>(w1_s + r * SW1 + kq);
        dst[0] = __floats2half2_rn(v.x, v.y);
        dst[1] = __floats2half2_rn(v.z, v.w);
    }
    for (int i = tid; i < 8 * 68; i += 512) c_s[i] = 0.0f;

    // ---- epilogue mapping: layer = tid>>8; (b, ul) = ((tid&255)>>2, tid&3)
    const int eL   = tid >> 8;
    const int eb   = (tid & 255) >> 2;
    const int eul  = tid & 3;
    const int ucol = blk * 4 + eul;
    float bia[4] = {0.f, 0.f, 0.f, 0.f};
    if (eL == 1) {
#pragma unroll
        for (int q = 0; q < 4; q++)
            bia[q] = b_ih1[q * 512 + ucol] + b_hh1[q * 512 + ucol];
    }

    // ---- ldmatrix base addresses ------------------------------------------
    const int rowoff = wm * 16 + (lane & 15);
    const int k8     = (lane >> 4) << 3;
    unsigned h0b = (unsigned)__cvta_generic_to_shared(h0_s);
    unsigned h1b = (unsigned)__cvta_generic_to_shared(h1_s);
    unsigned a0base = h0b + (unsigned)((rowoff * SHH + ks * 128 + k8) * 2);
    unsigned bw0    = (unsigned)__cvta_generic_to_shared(w0_s)
                    + (unsigned)(((lane & 15) * SHH + ks * 128 + k8) * 2);
    unsigned a1base = (ks < 2 ? h0b : h1b)
                    + (unsigned)((rowoff * SHH + (ks & 1) * 256 + k8) * 2);
    unsigned bw1    = (unsigned)__cvta_generic_to_shared(w1_s)
                    + (unsigned)(((lane & 15) * SW1 + ks * 256 + k8) * 2);

    unsigned* bar = &d_barrier;
    __syncthreads();

    for (int s = 1; s <= SEQT + 1; s++) {
        const bool do0 = (s <= SEQT);
        const bool do1 = (s >= 2);

        // ---- xg prefetch for L0 epilogue threads (independent of barrier)
        float px0 = 0.f, px1 = 0.f, px2 = 0.f, px3 = 0.f;
        if (eL == 0 && do0) {
            const float* xp = xg + (size_t)(s - 1) * (BATCH * G4)
                            + (size_t)eb * G4;
            px0 = xp[ucol];
            px1 = xp[512  + ucol];
            px2 = xp[1024 + ucol];
            px3 = xp[1536 + ucol];
        }

        // ---- one grid barrier per tick -------------------------------------
        if (tid == 0) bar_wait(bar, 128u * (unsigned)(s - 1));
        __syncthreads();

        // ---- stage h0[s-1] and h1[s-2] -------------------------------------
        {
            const uint4* s0 = (const uint4*)(d_h0seq + (size_t)(s - 1) * SEQH);
            int h1slot = (s >= 2) ? (s - 2) : 0;
            const uint4* s1 = (const uint4*)(d_h1seq + (size_t)h1slot * SEQH);
#pragma unroll
            for (int i = 0; i < 8; i++) {
                int idx = tid + i * 512;
                int b = idx >> 6, kc = idx & 63;
                *reinterpret_cast<uint4*>(h0_s + b * SHH + kc * 8) = s0[b * 64 + kc];
            }
#pragma unroll
            for (int i = 0; i < 8; i++) {
                int idx = tid + i * 512;
                int b = idx >> 6, kc = idx & 63;
                *reinterpret_cast<uint4*>(h1_s + b * SHH + kc * 8) = s1[b * 64 + kc];
            }
        }
        __syncthreads();

        // ---- L0 mma: 8 k16-iters ------------------------------------------
        float a00[4] = {0.f, 0.f, 0.f, 0.f};   // L0 cols 0-7
        float a01[4] = {0.f, 0.f, 0.f, 0.f};   // L0 cols 8-15
        if (do0) {
#pragma unroll
            for (int kk = 0; kk < 8; kk++) {
                unsigned ra0, ra1, ra2, ra3, rb0, rb1, rb2, rb3;
                LDSM4(ra0, ra1, ra2, ra3, a0base + kk * 32);
                LDSM4(rb0, rb1, rb2, rb3, bw0 + kk * 32);
                MMA16816(a00, ra0, ra1, ra2, ra3, rb0, rb2);
                MMA16816(a01, ra0, ra1, ra2, ra3, rb1, rb3);
            }
        }
        // ---- L1 mma: 16 k16-iters -------------------------------------------
        float a10[4] = {0.f, 0.f, 0.f, 0.f};
        float a11[4] = {0.f, 0.f, 0.f, 0.f};
#pragma unroll
        for (int kk = 0; kk < 16; kk++) {
            unsigned ra0, ra1, ra2, ra3, rb0, rb1, rb2, rb3;
            LDSM4(ra0, ra1, ra2, ra3, a1base + kk * 32);
            LDSM4(rb0, rb1, rb2, rb3, bw1 + kk * 32);
            MMA16816(a10, ra0, ra1, ra2, ra3, rb0, rb2);
            MMA16816(a11, ra0, ra1, ra2, ra3, rb1, rb3);
        }

        // ---- stage partials: g_s[(L*4+ks)*16 + col][b] ----------------------
        {
            int gb = wm * 16 + (lane >> 2);
            int c0 = (lane & 3) * 2;
            float* g0 = g_s + (size_t)(ks * 16) * 65;
            float* g1 = g_s + (size_t)((4 + ks) * 16) * 65;
            g0[(c0     ) * 65 + gb    ] = a00[0];
            g0[(c0 +  1) * 65 + gb    ] = a00[1];
            g0[(c0     ) * 65 + gb + 8] = a00[2];
            g0[(c0 +  1) * 65 + gb + 8] = a00[3];
            g0[(c0 +  8) * 65 + gb    ] = a01[0];
            g0[(c0 +  9) * 65 + gb    ] = a01[1];
            g0[(c0 +  8) * 65 + gb + 8] = a01[2];
            g0[(c0 +  9) * 65 + gb + 8] = a01[3];
            g1[(c0     ) * 65 + gb    ] = a10[0];
            g1[(c0 +  1) * 65 + gb    ] = a10[1];
            g1[(c0     ) * 65 + gb + 8] = a10[2];
            g1[(c0 +  1) * 65 + gb + 8] = a10[3];
            g1[(c0 +  8) * 65 + gb    ] = a11[0];
            g1[(c0 +  9) * 65 + gb    ] = a11[1];
            g1[(c0 +  8) * 65 + gb + 8] = a11[2];
            g1[(c0 +  9) * 65 + gb + 8] = a11[3];
        }
        __syncthreads();

        // ---- gates + cell update --------------------------------------------
        if ((eL == 0 && do0) || (eL == 1 && do1)) {
            float g[4];
#pragma unroll
            for (int q = 0; q < 4; q++) {
                int col = (eL * 4) * 16 + q * 4 + eul;   // base row in g_s
                float v = g_s[(col         ) * 65 + eb]
                        + g_s[(col + 16    ) * 65 + eb]
                        + g_s[(col + 32    ) * 65 + eb]
                        + g_s[(col + 48    ) * 65 + eb];
                g[q] = v;
            }
            if (eL == 0) {
                g[0] += px0; g[1] += px1; g[2] += px2; g[3] += px3;
            } else {
                g[0] += bia[0]; g[1] += bia[1]; g[2] += bia[2]; g[3] += bia[3];
            }

            float i_t = sigm_f(g[0]);
            float f_t = sigm_f(g[1]);
            float g_t = tanh_f(g[2]);
            float o_t = sigm_f(g[3]);

            int ci = (eL * 4 + eul) * 68 + eb;
            float cn = f_t * c_s[ci] + i_t * g_t;
            c_s[ci] = cn;
            float hv = o_t * tanh_f(cn);

            if (eL == 0) {
                d_h0seq[(size_t)s * SEQH + eb * 512 + ucol] = __float2half(hv);
            } else {
                d_h1seq[(size_t)(s - 1) * SEQH + eb * 512 + ucol] = __float2half(hv);
                if (s == SEQT + 1)
                    d_hlast[eb * 512 + ucol] = hv;
            }
        }
        __syncthreads();
        if (tid == 0) bar_red(bar);
    }
}

// ---------------------------------------------------------------------------
// kernel_launch
// ---------------------------------------------------------------------------
extern "C" void kernel_launch(void* const* d_in, const int* in_sizes, int n_in,
                              void* d_out, int out_size)
{
    const int*   X     = (const int*)  d_in[0];
    const float* emb   = (const float*)d_in[1];
    const float* w_ih0 = (const float*)d_in[2];
    const float* w_hh0 = (const float*)d_in[3];
    const float* b_ih0 = (const float*)d_in[4];
    const float* b_hh0 = (const float*)d_in[5];
    const float* w_ih1 = (const float*)d_in[6];
    const float* w_hh1 = (const float*)d_in[7];
    const float* b_ih1 = (const float*)d_in[8];
    const float* b_hh1 = (const float*)d_in[9];
    const float* Wout  = (const float*)d_in[10];
    const float* bout  = (const float*)d_in[11];
    float* out = (float*)d_out;

    float *xg, *hlast;
    __half *h0s, *h1s;
    cudaGetSymbolAddress((void**)&xg,    d_xg);
    cudaGetSymbolAddress((void**)&h0s,   d_h0seq);
    cudaGetSymbolAddress((void**)&h1s,   d_h1seq);
    cudaGetSymbolAddress((void**)&hlast, d_hlast);

    cudaFuncSetAttribute(lstm_merged,
                         cudaFuncAttributeMaxDynamicSharedMemorySize,
                         MERGED_SMEM);

    // 1) zero h slot-0 + barrier
    zero_h<<<32, 256>>>(h0s, h1s, SEQH);
    zero_bar<<<1, 32>>>();

    // 2) xg for layer 0 (embedding gather fused, tf32 mma)
    {
        dim3 grid(G4 / 128, MTOT / 128);
        gemm_mma2<<<grid, 512>>>(emb, w_ih0, xg, b_ih0, b_hh0, X,
                                 MTOT, G4, HIDN);
    }

    // 3) merged-cohort 2-layer recurrence (one barrier per tick)
    lstm_merged<<<128, 512, MERGED_SMEM>>>(xg, w_hh0, w_ih1, w_hh1,
                                           b_ih1, b_hh1);

    // 4) logits = h1_last @ W^T + b  (guarded tf32 mma)
    {
        dim3 grid((NCLS + 127) / 128, 1);
        gemm_mma2<<<grid, 512>>>(hlast, Wout, out, bout, nullptr, nullptr,
                                 BATCH, NCLS, HIDN);
    }
}